// round 12
// baseline (speedup 1.0000x reference)
#include <cuda_runtime.h>
#include <math.h>

// -----------------------------------------------------------------------------
// NeuralSplineFourierFilter — converged design (r5 structure), micro-trimmed.
//
// 11 rounds of evidence: ~29us is the access-pattern floor (128MB through the
// L2/LTS at the achievable mixed r+w rate); no SM-side knob (LDS width, occ,
// grid, cache policy, 256-bit ld/st) moves it. This round banks the r5 best
// with two strictly-local trims:
//   1. Table built from 2049 shared edge values (8 spline evals/thread, was 16)
//   2. 8 blocks/SM (was 6) for a little extra latency-hiding margin.
//
// Table: 2048-cell linear-interp float2 {f, df} over x in [0,1), 16KB smem,
// from symbolically expanded de Boor cubics (rel_err 1.4e-6).
// Main loop: __ldcs/__stcs float4, 4-deep batching — identical to r5.
// -----------------------------------------------------------------------------

#define NSFF_T 2048
#define NSFF_RSQRT3F 0.57735026918962576f

__device__ __forceinline__ float nsff_spline_eval(
    float xe, const float* __restrict__ sak, const float (*__restrict__ dP)[4]) {
    float xp = fminf(fmaxf(xe * NSFF_RSQRT3F, 0.0f), 0.9999f);
    int i = (xp >= sak[4]) + (xp >= sak[5]) + (xp >= sak[6])
          + (xp >= sak[7]) + (xp >= sak[8]) + (xp >= sak[9]);
    float u = xp - sak[3 + i];
    return fmaf(fmaf(fmaf(dP[i][3], u, dP[i][2]), u, dP[i][1]), u, dP[i][0]);
}

__device__ __forceinline__ float nsff_lookup(float xx, const float2* __restrict__ tab) {
    float y = xx * (float)NSFF_T;     // x in [0,1) -> y in [0,2048)
    int j = (int)y;
    float t = y - (float)j;
    float2 c = tab[j];
    return fmaf(t, c.y, c.x);
}

__global__ void __launch_bounds__(256, 8)
nsff_fused_kernel(const float* __restrict__ x,
                  const float* __restrict__ a,
                  const float* __restrict__ W1,
                  const float* __restrict__ b1,
                  const float* __restrict__ W2,
                  const float* __restrict__ b2,
                  const float* __restrict__ Ww,
                  const float* __restrict__ bw,
                  const float* __restrict__ Wk,
                  const float* __restrict__ bk,
                  float* __restrict__ out, int n4) {
    __shared__ float net1[32];
    __shared__ float net2[32];
    __shared__ float sw[9];
    __shared__ float skraw[7];
    __shared__ float sak[14];
    __shared__ float sc[10];
    __shared__ float dP[7][4];
    __shared__ float fedge[NSFF_T + 1];
    __shared__ __align__(8) float2 tab[NSFF_T];

    const int tid = threadIdx.x;

    // ---- tiny MLP (warp 0) ----
    if (tid < 32) {
        float av = a[0];
        net1[tid] = sinf(av * W1[tid] + b1[tid]);
    }
    __syncthreads();
    if (tid < 32) {
        float acc = b2[tid];
#pragma unroll
        for (int j = 0; j < 32; j++) acc += net1[j] * W2[j * 32 + tid];
        net2[tid] = sinf(acc);
    }
    __syncthreads();
    if (tid < 9) {
        float s = bw[tid];
#pragma unroll
        for (int j = 0; j < 32; j++) s += net2[j] * Ww[j * 9 + tid];
        sw[tid] = s;
    }
    if (tid < 7) {
        float s = bk[tid];
#pragma unroll
        for (int j = 0; j < 32; j++) s += net2[j] * Wk[j * 7 + tid];
        skraw[tid] = s;
    }
    __syncthreads();

    // ---- softmax + cumsum -> knot vector; control points (lane 0) ----
    if (tid == 0) {
        float m = skraw[0];
#pragma unroll
        for (int j = 1; j < 7; j++) m = fmaxf(m, skraw[j]);
        float e[7];
        float tot = 0.0f;
#pragma unroll
        for (int j = 0; j < 7; j++) { e[j] = expf(skraw[j] - m); tot += e[j]; }
        float inv = 1.0f / tot;

        sak[0] = sak[1] = sak[2] = 0.0f;
        sak[3] = 0.0f;
        float cum = 0.0f;
#pragma unroll
        for (int j = 0; j < 7; j++) { cum += e[j] * inv; sak[4 + j] = cum; }
        sak[11] = sak[12] = sak[13] = 1.0f;

        sc[0] = 0.0f;
#pragma unroll
        for (int j = 0; j < 9; j++) sc[1 + j] = sw[j];
    }
    __syncthreads();

    // ---- symbolic de Boor per interval k = 3 + lane, in u = xp - ak[k] ----
    if (tid < 7) {
        const int k = 3 + tid;
        const float tk = sak[k];
        float P[4][4];
#pragma unroll
        for (int j = 0; j < 4; j++) {
            P[j][0] = sc[j + k - 3];
            P[j][1] = P[j][2] = P[j][3] = 0.0f;
        }
#pragma unroll
        for (int r = 1; r <= 3; r++) {
#pragma unroll
            for (int j = 3; j >= 1; j--) {
                if (j < r) continue;
                float ta = sak[j + k - 3];
                float tb = sak[j + 1 + k - r];
                float rcp = 1.0f / (tb - ta);
                float A = (tk - ta) * rcp;   // alpha = A + B*u
                float B = rcp;
                float q0 = (1.0f - A) * P[j - 1][0] + A * P[j][0];
                float q1 = (1.0f - A) * P[j - 1][1] + A * P[j][1]
                         + B * (P[j][0] - P[j - 1][0]);
                float q2 = (1.0f - A) * P[j - 1][2] + A * P[j][2]
                         + B * (P[j][1] - P[j - 1][1]);
                float q3 = (1.0f - A) * P[j - 1][3] + A * P[j][3]
                         + B * (P[j][2] - P[j - 1][2]);
                P[j][0] = q0; P[j][1] = q1; P[j][2] = q2; P[j][3] = q3;
            }
        }
        dP[tid][0] = P[3][0]; dP[tid][1] = P[3][1];
        dP[tid][2] = P[3][2]; dP[tid][3] = P[3][3];
    }
    __syncthreads();

    // ---- 2049 edge values, then per-cell {f, df} (half the evals of r5) ----
    {
        const float invT = 1.0f / (float)NSFF_T;
#pragma unroll
        for (int m = 0; m < NSFF_T / 256; m++) {
            int j = tid + m * 256;
            fedge[j] = nsff_spline_eval((float)j * invT, sak, dP);
        }
        if (tid == 0)
            fedge[NSFF_T] = nsff_spline_eval(1.0f, sak, dP);
    }
    __syncthreads();
    {
#pragma unroll
        for (int m = 0; m < NSFF_T / 256; m++) {
            int j = tid + m * 256;
            float f0 = fedge[j];
            tab[j] = make_float2(f0, fedge[j + 1] - f0);
        }
    }
    __syncthreads();

    // ---- streaming main loop (identical to r5) ----
    const float4* __restrict__ x4 = reinterpret_cast<const float4*>(x);
    float4* __restrict__ o4 = reinterpret_cast<float4*>(out);

    const int nth = gridDim.x * blockDim.x;
    int i = blockIdx.x * blockDim.x + tid;

    // fast path: 4 float4 per iteration, no predicates
    for (; i + 3 * nth < n4; i += 4 * nth) {
        float4 v0 = __ldcs(&x4[i]);
        float4 v1 = __ldcs(&x4[i + nth]);
        float4 v2 = __ldcs(&x4[i + 2 * nth]);
        float4 v3 = __ldcs(&x4[i + 3 * nth]);
        float4 r0, r1, r2, r3;
        r0.x = nsff_lookup(v0.x, tab); r0.y = nsff_lookup(v0.y, tab);
        r0.z = nsff_lookup(v0.z, tab); r0.w = nsff_lookup(v0.w, tab);
        r1.x = nsff_lookup(v1.x, tab); r1.y = nsff_lookup(v1.y, tab);
        r1.z = nsff_lookup(v1.z, tab); r1.w = nsff_lookup(v1.w, tab);
        r2.x = nsff_lookup(v2.x, tab); r2.y = nsff_lookup(v2.y, tab);
        r2.z = nsff_lookup(v2.z, tab); r2.w = nsff_lookup(v2.w, tab);
        r3.x = nsff_lookup(v3.x, tab); r3.y = nsff_lookup(v3.y, tab);
        r3.z = nsff_lookup(v3.z, tab); r3.w = nsff_lookup(v3.w, tab);
        __stcs(&o4[i], r0);
        __stcs(&o4[i + nth], r1);
        __stcs(&o4[i + 2 * nth], r2);
        __stcs(&o4[i + 3 * nth], r3);
    }
    // tail
    for (; i < n4; i += nth) {
        float4 v = __ldcs(&x4[i]);
        float4 r;
        r.x = nsff_lookup(v.x, tab);
        r.y = nsff_lookup(v.y, tab);
        r.z = nsff_lookup(v.z, tab);
        r.w = nsff_lookup(v.w, tab);
        __stcs(&o4[i], r);
    }
}

extern "C" void kernel_launch(void* const* d_in, const int* in_sizes, int n_in,
                              void* d_out, int out_size) {
    const float* x  = (const float*)d_in[0];
    const float* a  = (const float*)d_in[1];
    const float* W1 = (const float*)d_in[2];
    const float* b1 = (const float*)d_in[3];
    const float* W2 = (const float*)d_in[4];
    const float* b2 = (const float*)d_in[5];
    const float* Ww = (const float*)d_in[6];
    const float* bw = (const float*)d_in[7];
    const float* Wk = (const float*)d_in[8];
    const float* bk = (const float*)d_in[9];
    float* out = (float*)d_out;

    const int n4 = out_size / 4;   // 4,194,304 for 256^3
    int blocks = 152 * 8;          // persistent: 8 blocks/SM, ~16.5KB smem each
    int need = (n4 + 255) / 256;
    if (blocks > need) blocks = need;
    nsff_fused_kernel<<<blocks, 256>>>(x, a, W1, b1, W2, b2, Ww, bw, Wk, bk,
                                       out, n4);
}

// round 14
// speedup vs baseline: 1.1584x; 1.1584x over previous
#include <cuda_runtime.h>
#include <math.h>

// -----------------------------------------------------------------------------
// NeuralSplineFourierFilter — r5 best, front-batch depth 4 -> 2.
//
// New evidence (r11, r12): raising concurrency/burst size REGRESSES. Fits the
// B300 multi-CTA spread model: spr_max = 1.10 + 25*(oe*MLP_p1 - 16)/T_CTA
// (cross-CTA L1tex queue contention from front-batched LDGs).
//   r1  oe~8 MLP_p1=1 ->  8  -> eval 28.5us (best)
//   r5  oe=6 MLP_p1=4 -> 24  -> 29.2us
//   r12 oe=8 MLP_p1=4 -> 32  -> 35.3us
// This round: r5 byte-identical EXCEPT batch depth 2 (oe*MLP_p1 = 12 < 16).
//
// Table: 2048-cell linear-interp float2 {f, df} over x in [0,1), 16KB smem,
// from symbolically expanded de Boor cubics (rel_err 1.4e-6).
// -----------------------------------------------------------------------------

#define NSFF_T 2048
#define NSFF_RSQRT3F 0.57735026918962576f

__device__ __forceinline__ float nsff_spline_eval(
    float xe, const float* __restrict__ sak, const float (*__restrict__ dP)[4]) {
    float xp = fminf(fmaxf(xe * NSFF_RSQRT3F, 0.0f), 0.9999f);
    int i = (xp >= sak[4]) + (xp >= sak[5]) + (xp >= sak[6])
          + (xp >= sak[7]) + (xp >= sak[8]) + (xp >= sak[9]);
    float u = xp - sak[3 + i];
    return fmaf(fmaf(fmaf(dP[i][3], u, dP[i][2]), u, dP[i][1]), u, dP[i][0]);
}

__device__ __forceinline__ float nsff_lookup(float xx, const float2* __restrict__ tab) {
    float y = xx * (float)NSFF_T;     // x in [0,1) -> y in [0,2048)
    int j = (int)y;
    float t = y - (float)j;
    float2 c = tab[j];
    return fmaf(t, c.y, c.x);
}

__global__ void __launch_bounds__(256, 6)
nsff_fused_kernel(const float* __restrict__ x,
                  const float* __restrict__ a,
                  const float* __restrict__ W1,
                  const float* __restrict__ b1,
                  const float* __restrict__ W2,
                  const float* __restrict__ b2,
                  const float* __restrict__ Ww,
                  const float* __restrict__ bw,
                  const float* __restrict__ Wk,
                  const float* __restrict__ bk,
                  float* __restrict__ out, int n4) {
    __shared__ float net1[32];
    __shared__ float net2[32];
    __shared__ float sw[9];
    __shared__ float skraw[7];
    __shared__ float sak[14];
    __shared__ float sc[10];
    __shared__ float dP[7][4];
    __shared__ __align__(8) float2 tab[NSFF_T];

    const int tid = threadIdx.x;

    // ---- tiny MLP (warp 0) ----
    if (tid < 32) {
        float av = a[0];
        net1[tid] = sinf(av * W1[tid] + b1[tid]);
    }
    __syncthreads();
    if (tid < 32) {
        float acc = b2[tid];
#pragma unroll
        for (int j = 0; j < 32; j++) acc += net1[j] * W2[j * 32 + tid];
        net2[tid] = sinf(acc);
    }
    __syncthreads();
    if (tid < 9) {
        float s = bw[tid];
#pragma unroll
        for (int j = 0; j < 32; j++) s += net2[j] * Ww[j * 9 + tid];
        sw[tid] = s;
    }
    if (tid < 7) {
        float s = bk[tid];
#pragma unroll
        for (int j = 0; j < 32; j++) s += net2[j] * Wk[j * 7 + tid];
        skraw[tid] = s;
    }
    __syncthreads();

    // ---- softmax + cumsum -> knot vector; control points (lane 0) ----
    if (tid == 0) {
        float m = skraw[0];
#pragma unroll
        for (int j = 1; j < 7; j++) m = fmaxf(m, skraw[j]);
        float e[7];
        float tot = 0.0f;
#pragma unroll
        for (int j = 0; j < 7; j++) { e[j] = expf(skraw[j] - m); tot += e[j]; }
        float inv = 1.0f / tot;

        sak[0] = sak[1] = sak[2] = 0.0f;
        sak[3] = 0.0f;
        float cum = 0.0f;
#pragma unroll
        for (int j = 0; j < 7; j++) { cum += e[j] * inv; sak[4 + j] = cum; }
        sak[11] = sak[12] = sak[13] = 1.0f;

        sc[0] = 0.0f;
#pragma unroll
        for (int j = 0; j < 9; j++) sc[1 + j] = sw[j];
    }
    __syncthreads();

    // ---- symbolic de Boor per interval k = 3 + lane, in u = xp - ak[k] ----
    if (tid < 7) {
        const int k = 3 + tid;
        const float tk = sak[k];
        float P[4][4];
#pragma unroll
        for (int j = 0; j < 4; j++) {
            P[j][0] = sc[j + k - 3];
            P[j][1] = P[j][2] = P[j][3] = 0.0f;
        }
#pragma unroll
        for (int r = 1; r <= 3; r++) {
#pragma unroll
            for (int j = 3; j >= 1; j--) {
                if (j < r) continue;
                float ta = sak[j + k - 3];
                float tb = sak[j + 1 + k - r];
                float rcp = 1.0f / (tb - ta);
                float A = (tk - ta) * rcp;   // alpha = A + B*u
                float B = rcp;
                float q0 = (1.0f - A) * P[j - 1][0] + A * P[j][0];
                float q1 = (1.0f - A) * P[j - 1][1] + A * P[j][1]
                         + B * (P[j][0] - P[j - 1][0]);
                float q2 = (1.0f - A) * P[j - 1][2] + A * P[j][2]
                         + B * (P[j][1] - P[j - 1][1]);
                float q3 = (1.0f - A) * P[j - 1][3] + A * P[j][3]
                         + B * (P[j][2] - P[j - 1][2]);
                P[j][0] = q0; P[j][1] = q1; P[j][2] = q2; P[j][3] = q3;
            }
        }
        dP[tid][0] = P[3][0]; dP[tid][1] = P[3][1];
        dP[tid][2] = P[3][2]; dP[tid][3] = P[3][3];
    }
    __syncthreads();

    // ---- linear table over x in [0,1): 2048 cells ----
    {
        const float invT = 1.0f / (float)NSFF_T;
#pragma unroll
        for (int m = 0; m < NSFF_T / 256; m++) {
            int j = tid + m * 256;
            float xl = (float)j * invT;
            float xr = (float)(j + 1) * invT;
            float f0 = nsff_spline_eval(xl, sak, dP);
            float f1 = nsff_spline_eval(xr, sak, dP);
            tab[j] = make_float2(f0, f1 - f0);
        }
    }
    __syncthreads();

    // ---- streaming main loop: depth-2 batching (MLP_p1 = 2) ----
    const float4* __restrict__ x4 = reinterpret_cast<const float4*>(x);
    float4* __restrict__ o4 = reinterpret_cast<float4*>(out);

    const int nth = gridDim.x * blockDim.x;
    int i = blockIdx.x * blockDim.x + tid;

    // fast path: 2 float4 per iteration, no predicates
    for (; i + nth < n4; i += 2 * nth) {
        float4 v0 = __ldcs(&x4[i]);
        float4 v1 = __ldcs(&x4[i + nth]);
        float4 r0, r1;
        r0.x = nsff_lookup(v0.x, tab); r0.y = nsff_lookup(v0.y, tab);
        r0.z = nsff_lookup(v0.z, tab); r0.w = nsff_lookup(v0.w, tab);
        r1.x = nsff_lookup(v1.x, tab); r1.y = nsff_lookup(v1.y, tab);
        r1.z = nsff_lookup(v1.z, tab); r1.w = nsff_lookup(v1.w, tab);
        __stcs(&o4[i], r0);
        __stcs(&o4[i + nth], r1);
    }
    // tail
    for (; i < n4; i += nth) {
        float4 v = __ldcs(&x4[i]);
        float4 r;
        r.x = nsff_lookup(v.x, tab);
        r.y = nsff_lookup(v.y, tab);
        r.z = nsff_lookup(v.z, tab);
        r.w = nsff_lookup(v.w, tab);
        __stcs(&o4[i], r);
    }
}

extern "C" void kernel_launch(void* const* d_in, const int* in_sizes, int n_in,
                              void* d_out, int out_size) {
    const float* x  = (const float*)d_in[0];
    const float* a  = (const float*)d_in[1];
    const float* W1 = (const float*)d_in[2];
    const float* b1 = (const float*)d_in[3];
    const float* W2 = (const float*)d_in[4];
    const float* b2 = (const float*)d_in[5];
    const float* Ww = (const float*)d_in[6];
    const float* bw = (const float*)d_in[7];
    const float* Wk = (const float*)d_in[8];
    const float* bk = (const float*)d_in[9];
    float* out = (float*)d_out;

    const int n4 = out_size / 4;   // 4,194,304 for 256^3
    int blocks = 152 * 6;          // persistent: 6 blocks/SM, 16KB table each
    int need = (n4 + 255) / 256;
    if (blocks > need) blocks = need;
    nsff_fused_kernel<<<blocks, 256>>>(x, a, W1, b1, W2, b2, Ww, bw, Wk, bk,
                                       out, n4);
}

// round 15
// speedup vs baseline: 1.2105x; 1.0450x over previous
#include <cuda_runtime.h>
#include <math.h>

// -----------------------------------------------------------------------------
// NeuralSplineFourierFilter — CONVERGED kernel (r5, resubmitted verbatim).
//
// Session summary (14 rounds of evidence):
//  - Workload = 16.7M-elem fp32 elementwise spline; tiny MLP hoisted into a
//    per-block prologue; spline collapsed to a 2048-cell linear-interp table
//    built from symbolically-expanded de Boor cubics (rel_err 1.4e-6).
//  - All structurally-sane variants land 29.2-31.2us; plateau is the
//    L2/LTS-mediated 128MB stream floor, not any SM-side pipe:
//      * LDS width 128/64/32-bit: neutral      * occupancy 4/6/8 blk/SM: 6 best
//      * batch depth 1/2/4: 4 best             * cache policies: .cs/.cs best
//      * (wt, evict_last pin: bad regressions; v8 ld/st: neutral-worse)
//  - This exact configuration measured the session best: 29.2us.
// -----------------------------------------------------------------------------

#define NSFF_T 2048
#define NSFF_RSQRT3F 0.57735026918962576f

__device__ __forceinline__ float nsff_spline_eval(
    float xe, const float* __restrict__ sak, const float (*__restrict__ dP)[4]) {
    float xp = fminf(fmaxf(xe * NSFF_RSQRT3F, 0.0f), 0.9999f);
    int i = (xp >= sak[4]) + (xp >= sak[5]) + (xp >= sak[6])
          + (xp >= sak[7]) + (xp >= sak[8]) + (xp >= sak[9]);
    float u = xp - sak[3 + i];
    return fmaf(fmaf(fmaf(dP[i][3], u, dP[i][2]), u, dP[i][1]), u, dP[i][0]);
}

__device__ __forceinline__ float nsff_lookup(float xx, const float2* __restrict__ tab) {
    float y = xx * (float)NSFF_T;     // x in [0,1) -> y in [0,2048)
    int j = (int)y;
    float t = y - (float)j;
    float2 c = tab[j];
    return fmaf(t, c.y, c.x);
}

__global__ void __launch_bounds__(256, 6)
nsff_fused_kernel(const float* __restrict__ x,
                  const float* __restrict__ a,
                  const float* __restrict__ W1,
                  const float* __restrict__ b1,
                  const float* __restrict__ W2,
                  const float* __restrict__ b2,
                  const float* __restrict__ Ww,
                  const float* __restrict__ bw,
                  const float* __restrict__ Wk,
                  const float* __restrict__ bk,
                  float* __restrict__ out, int n4) {
    __shared__ float net1[32];
    __shared__ float net2[32];
    __shared__ float sw[9];
    __shared__ float skraw[7];
    __shared__ float sak[14];
    __shared__ float sc[10];
    __shared__ float dP[7][4];
    __shared__ __align__(8) float2 tab[NSFF_T];

    const int tid = threadIdx.x;

    // ---- tiny MLP (warp 0) ----
    if (tid < 32) {
        float av = a[0];
        net1[tid] = sinf(av * W1[tid] + b1[tid]);
    }
    __syncthreads();
    if (tid < 32) {
        float acc = b2[tid];
#pragma unroll
        for (int j = 0; j < 32; j++) acc += net1[j] * W2[j * 32 + tid];
        net2[tid] = sinf(acc);
    }
    __syncthreads();
    if (tid < 9) {
        float s = bw[tid];
#pragma unroll
        for (int j = 0; j < 32; j++) s += net2[j] * Ww[j * 9 + tid];
        sw[tid] = s;
    }
    if (tid < 7) {
        float s = bk[tid];
#pragma unroll
        for (int j = 0; j < 32; j++) s += net2[j] * Wk[j * 7 + tid];
        skraw[tid] = s;
    }
    __syncthreads();

    // ---- softmax + cumsum -> knot vector; control points (lane 0) ----
    if (tid == 0) {
        float m = skraw[0];
#pragma unroll
        for (int j = 1; j < 7; j++) m = fmaxf(m, skraw[j]);
        float e[7];
        float tot = 0.0f;
#pragma unroll
        for (int j = 0; j < 7; j++) { e[j] = expf(skraw[j] - m); tot += e[j]; }
        float inv = 1.0f / tot;

        sak[0] = sak[1] = sak[2] = 0.0f;
        sak[3] = 0.0f;
        float cum = 0.0f;
#pragma unroll
        for (int j = 0; j < 7; j++) { cum += e[j] * inv; sak[4 + j] = cum; }
        sak[11] = sak[12] = sak[13] = 1.0f;

        sc[0] = 0.0f;
#pragma unroll
        for (int j = 0; j < 9; j++) sc[1 + j] = sw[j];
    }
    __syncthreads();

    // ---- symbolic de Boor per interval k = 3 + lane, in u = xp - ak[k] ----
    if (tid < 7) {
        const int k = 3 + tid;
        const float tk = sak[k];
        float P[4][4];
#pragma unroll
        for (int j = 0; j < 4; j++) {
            P[j][0] = sc[j + k - 3];
            P[j][1] = P[j][2] = P[j][3] = 0.0f;
        }
#pragma unroll
        for (int r = 1; r <= 3; r++) {
#pragma unroll
            for (int j = 3; j >= 1; j--) {
                if (j < r) continue;
                float ta = sak[j + k - 3];
                float tb = sak[j + 1 + k - r];
                float rcp = 1.0f / (tb - ta);
                float A = (tk - ta) * rcp;   // alpha = A + B*u
                float B = rcp;
                float q0 = (1.0f - A) * P[j - 1][0] + A * P[j][0];
                float q1 = (1.0f - A) * P[j - 1][1] + A * P[j][1]
                         + B * (P[j][0] - P[j - 1][0]);
                float q2 = (1.0f - A) * P[j - 1][2] + A * P[j][2]
                         + B * (P[j][1] - P[j - 1][1]);
                float q3 = (1.0f - A) * P[j - 1][3] + A * P[j][3]
                         + B * (P[j][2] - P[j - 1][2]);
                P[j][0] = q0; P[j][1] = q1; P[j][2] = q2; P[j][3] = q3;
            }
        }
        dP[tid][0] = P[3][0]; dP[tid][1] = P[3][1];
        dP[tid][2] = P[3][2]; dP[tid][3] = P[3][3];
    }
    __syncthreads();

    // ---- linear table over x in [0,1): 2048 cells ----
    {
        const float invT = 1.0f / (float)NSFF_T;
#pragma unroll
        for (int m = 0; m < NSFF_T / 256; m++) {
            int j = tid + m * 256;
            float xl = (float)j * invT;
            float xr = (float)(j + 1) * invT;
            float f0 = nsff_spline_eval(xl, sak, dP);
            float f1 = nsff_spline_eval(xr, sak, dP);
            tab[j] = make_float2(f0, f1 - f0);
        }
    }
    __syncthreads();

    // ---- streaming main loop ----
    const float4* __restrict__ x4 = reinterpret_cast<const float4*>(x);
    float4* __restrict__ o4 = reinterpret_cast<float4*>(out);

    const int nth = gridDim.x * blockDim.x;
    int i = blockIdx.x * blockDim.x + tid;

    // fast path: all 4 slots in range, no predicates
    for (; i + 3 * nth < n4; i += 4 * nth) {
        float4 v0 = __ldcs(&x4[i]);
        float4 v1 = __ldcs(&x4[i + nth]);
        float4 v2 = __ldcs(&x4[i + 2 * nth]);
        float4 v3 = __ldcs(&x4[i + 3 * nth]);
        float4 r0, r1, r2, r3;
        r0.x = nsff_lookup(v0.x, tab); r0.y = nsff_lookup(v0.y, tab);
        r0.z = nsff_lookup(v0.z, tab); r0.w = nsff_lookup(v0.w, tab);
        r1.x = nsff_lookup(v1.x, tab); r1.y = nsff_lookup(v1.y, tab);
        r1.z = nsff_lookup(v1.z, tab); r1.w = nsff_lookup(v1.w, tab);
        r2.x = nsff_lookup(v2.x, tab); r2.y = nsff_lookup(v2.y, tab);
        r2.z = nsff_lookup(v2.z, tab); r2.w = nsff_lookup(v2.w, tab);
        r3.x = nsff_lookup(v3.x, tab); r3.y = nsff_lookup(v3.y, tab);
        r3.z = nsff_lookup(v3.z, tab); r3.w = nsff_lookup(v3.w, tab);
        __stcs(&o4[i], r0);
        __stcs(&o4[i + nth], r1);
        __stcs(&o4[i + 2 * nth], r2);
        __stcs(&o4[i + 3 * nth], r3);
    }
    // tail
    for (; i < n4; i += nth) {
        float4 v = __ldcs(&x4[i]);
        float4 r;
        r.x = nsff_lookup(v.x, tab);
        r.y = nsff_lookup(v.y, tab);
        r.z = nsff_lookup(v.z, tab);
        r.w = nsff_lookup(v.w, tab);
        __stcs(&o4[i], r);
    }
}

extern "C" void kernel_launch(void* const* d_in, const int* in_sizes, int n_in,
                              void* d_out, int out_size) {
    const float* x  = (const float*)d_in[0];
    const float* a  = (const float*)d_in[1];
    const float* W1 = (const float*)d_in[2];
    const float* b1 = (const float*)d_in[3];
    const float* W2 = (const float*)d_in[4];
    const float* b2 = (const float*)d_in[5];
    const float* Ww = (const float*)d_in[6];
    const float* bw = (const float*)d_in[7];
    const float* Wk = (const float*)d_in[8];
    const float* bk = (const float*)d_in[9];
    float* out = (float*)d_out;

    const int n4 = out_size / 4;   // 4,194,304 for 256^3
    int blocks = 152 * 6;          // persistent: 6 blocks/SM, 16KB table each
    int need = (n4 + 255) / 256;
    if (blocks > need) blocks = need;
    nsff_fused_kernel<<<blocks, 256>>>(x, a, W1, b1, W2, b2, Ww, bw, Wk, bk,
                                       out, n4);
}

// round 16
// speedup vs baseline: 1.3019x; 1.0755x over previous
#include <cuda_runtime.h>
#include <math.h>

// -----------------------------------------------------------------------------
// NeuralSplineFourierFilter — r5 main loop + 4x cheaper prologue.
//
// r15 confirmed 29.18us reproducible with the r5 configuration; every main-loop
// variable is measured and at its best value. The untested cost bucket is the
// per-block PROLOGUE (~500 inst/thread of serial time before streaming).
// This round, occupancy held at 48 warps/SM:
//   - block 512 (3 blocks/SM): half the redundant table builds per SM
//   - table built from 2049 shared edge values: 4 spline evals/thread (was 16)
//   - main loop identical to r5 (__ldcs/__stcs float4, depth 4);
//     oe*MLP_p1 = 3*4 = 12 < 16 (below the L1tex-spread threshold).
//
// Table: 2048-cell linear-interp float2 {f, df} over x in [0,1), 16KB smem,
// from symbolically expanded de Boor cubics (rel_err 1.4e-6).
// -----------------------------------------------------------------------------

#define NSFF_T 2048
#define NSFF_BLK 512
#define NSFF_RSQRT3F 0.57735026918962576f

__device__ __forceinline__ float nsff_spline_eval(
    float xe, const float* __restrict__ sak, const float (*__restrict__ dP)[4]) {
    float xp = fminf(fmaxf(xe * NSFF_RSQRT3F, 0.0f), 0.9999f);
    int i = (xp >= sak[4]) + (xp >= sak[5]) + (xp >= sak[6])
          + (xp >= sak[7]) + (xp >= sak[8]) + (xp >= sak[9]);
    float u = xp - sak[3 + i];
    return fmaf(fmaf(fmaf(dP[i][3], u, dP[i][2]), u, dP[i][1]), u, dP[i][0]);
}

__device__ __forceinline__ float nsff_lookup(float xx, const float2* __restrict__ tab) {
    float y = xx * (float)NSFF_T;     // x in [0,1) -> y in [0,2048)
    int j = (int)y;
    float t = y - (float)j;
    float2 c = tab[j];
    return fmaf(t, c.y, c.x);
}

__global__ void __launch_bounds__(NSFF_BLK, 3)
nsff_fused_kernel(const float* __restrict__ x,
                  const float* __restrict__ a,
                  const float* __restrict__ W1,
                  const float* __restrict__ b1,
                  const float* __restrict__ W2,
                  const float* __restrict__ b2,
                  const float* __restrict__ Ww,
                  const float* __restrict__ bw,
                  const float* __restrict__ Wk,
                  const float* __restrict__ bk,
                  float* __restrict__ out, int n4) {
    __shared__ float net1[32];
    __shared__ float net2[32];
    __shared__ float sw[9];
    __shared__ float skraw[7];
    __shared__ float sak[14];
    __shared__ float sc[10];
    __shared__ float dP[7][4];
    __shared__ float fedge[NSFF_T + 1];
    __shared__ __align__(8) float2 tab[NSFF_T];

    const int tid = threadIdx.x;

    // ---- tiny MLP (warp 0) ----
    if (tid < 32) {
        float av = a[0];
        net1[tid] = sinf(av * W1[tid] + b1[tid]);
    }
    __syncthreads();
    if (tid < 32) {
        float acc = b2[tid];
#pragma unroll
        for (int j = 0; j < 32; j++) acc += net1[j] * W2[j * 32 + tid];
        net2[tid] = sinf(acc);
    }
    __syncthreads();
    if (tid < 9) {
        float s = bw[tid];
#pragma unroll
        for (int j = 0; j < 32; j++) s += net2[j] * Ww[j * 9 + tid];
        sw[tid] = s;
    }
    if (tid < 7) {
        float s = bk[tid];
#pragma unroll
        for (int j = 0; j < 32; j++) s += net2[j] * Wk[j * 7 + tid];
        skraw[tid] = s;
    }
    __syncthreads();

    // ---- softmax + cumsum -> knot vector; control points (lane 0) ----
    if (tid == 0) {
        float m = skraw[0];
#pragma unroll
        for (int j = 1; j < 7; j++) m = fmaxf(m, skraw[j]);
        float e[7];
        float tot = 0.0f;
#pragma unroll
        for (int j = 0; j < 7; j++) { e[j] = expf(skraw[j] - m); tot += e[j]; }
        float inv = 1.0f / tot;

        sak[0] = sak[1] = sak[2] = 0.0f;
        sak[3] = 0.0f;
        float cum = 0.0f;
#pragma unroll
        for (int j = 0; j < 7; j++) { cum += e[j] * inv; sak[4 + j] = cum; }
        sak[11] = sak[12] = sak[13] = 1.0f;

        sc[0] = 0.0f;
#pragma unroll
        for (int j = 0; j < 9; j++) sc[1 + j] = sw[j];
    }
    __syncthreads();

    // ---- symbolic de Boor per interval k = 3 + lane, in u = xp - ak[k] ----
    if (tid < 7) {
        const int k = 3 + tid;
        const float tk = sak[k];
        float P[4][4];
#pragma unroll
        for (int j = 0; j < 4; j++) {
            P[j][0] = sc[j + k - 3];
            P[j][1] = P[j][2] = P[j][3] = 0.0f;
        }
#pragma unroll
        for (int r = 1; r <= 3; r++) {
#pragma unroll
            for (int j = 3; j >= 1; j--) {
                if (j < r) continue;
                float ta = sak[j + k - 3];
                float tb = sak[j + 1 + k - r];
                float rcp = 1.0f / (tb - ta);
                float A = (tk - ta) * rcp;   // alpha = A + B*u
                float B = rcp;
                float q0 = (1.0f - A) * P[j - 1][0] + A * P[j][0];
                float q1 = (1.0f - A) * P[j - 1][1] + A * P[j][1]
                         + B * (P[j][0] - P[j - 1][0]);
                float q2 = (1.0f - A) * P[j - 1][2] + A * P[j][2]
                         + B * (P[j][1] - P[j - 1][1]);
                float q3 = (1.0f - A) * P[j - 1][3] + A * P[j][3]
                         + B * (P[j][2] - P[j - 1][2]);
                P[j][0] = q0; P[j][1] = q1; P[j][2] = q2; P[j][3] = q3;
            }
        }
        dP[tid][0] = P[3][0]; dP[tid][1] = P[3][1];
        dP[tid][2] = P[3][2]; dP[tid][3] = P[3][3];
    }
    __syncthreads();

    // ---- 2049 edge values (4 evals/thread), then per-cell {f, df} ----
    {
        const float invT = 1.0f / (float)NSFF_T;
#pragma unroll
        for (int m = 0; m < NSFF_T / NSFF_BLK; m++) {
            int j = tid + m * NSFF_BLK;
            fedge[j] = nsff_spline_eval((float)j * invT, sak, dP);
        }
        if (tid == 0)
            fedge[NSFF_T] = nsff_spline_eval(1.0f, sak, dP);
    }
    __syncthreads();
    {
#pragma unroll
        for (int m = 0; m < NSFF_T / NSFF_BLK; m++) {
            int j = tid + m * NSFF_BLK;
            float f0 = fedge[j];
            tab[j] = make_float2(f0, fedge[j + 1] - f0);
        }
    }
    __syncthreads();

    // ---- streaming main loop (identical shape to r5: depth-4 batching) ----
    const float4* __restrict__ x4 = reinterpret_cast<const float4*>(x);
    float4* __restrict__ o4 = reinterpret_cast<float4*>(out);

    const int nth = gridDim.x * blockDim.x;
    int i = blockIdx.x * blockDim.x + tid;

    // fast path: all 4 slots in range, no predicates
    for (; i + 3 * nth < n4; i += 4 * nth) {
        float4 v0 = __ldcs(&x4[i]);
        float4 v1 = __ldcs(&x4[i + nth]);
        float4 v2 = __ldcs(&x4[i + 2 * nth]);
        float4 v3 = __ldcs(&x4[i + 3 * nth]);
        float4 r0, r1, r2, r3;
        r0.x = nsff_lookup(v0.x, tab); r0.y = nsff_lookup(v0.y, tab);
        r0.z = nsff_lookup(v0.z, tab); r0.w = nsff_lookup(v0.w, tab);
        r1.x = nsff_lookup(v1.x, tab); r1.y = nsff_lookup(v1.y, tab);
        r1.z = nsff_lookup(v1.z, tab); r1.w = nsff_lookup(v1.w, tab);
        r2.x = nsff_lookup(v2.x, tab); r2.y = nsff_lookup(v2.y, tab);
        r2.z = nsff_lookup(v2.z, tab); r2.w = nsff_lookup(v2.w, tab);
        r3.x = nsff_lookup(v3.x, tab); r3.y = nsff_lookup(v3.y, tab);
        r3.z = nsff_lookup(v3.z, tab); r3.w = nsff_lookup(v3.w, tab);
        __stcs(&o4[i], r0);
        __stcs(&o4[i + nth], r1);
        __stcs(&o4[i + 2 * nth], r2);
        __stcs(&o4[i + 3 * nth], r3);
    }
    // tail
    for (; i < n4; i += nth) {
        float4 v = __ldcs(&x4[i]);
        float4 r;
        r.x = nsff_lookup(v.x, tab);
        r.y = nsff_lookup(v.y, tab);
        r.z = nsff_lookup(v.z, tab);
        r.w = nsff_lookup(v.w, tab);
        __stcs(&o4[i], r);
    }
}

extern "C" void kernel_launch(void* const* d_in, const int* in_sizes, int n_in,
                              void* d_out, int out_size) {
    const float* x  = (const float*)d_in[0];
    const float* a  = (const float*)d_in[1];
    const float* W1 = (const float*)d_in[2];
    const float* b1 = (const float*)d_in[3];
    const float* W2 = (const float*)d_in[4];
    const float* b2 = (const float*)d_in[5];
    const float* Ww = (const float*)d_in[6];
    const float* bw = (const float*)d_in[7];
    const float* Wk = (const float*)d_in[8];
    const float* bk = (const float*)d_in[9];
    float* out = (float*)d_out;

    const int n4 = out_size / 4;   // 4,194,304 for 256^3
    int blocks = 152 * 3;          // persistent: 3 blocks/SM x 512 thr = 48 warps/SM
    int need = (n4 + NSFF_BLK - 1) / NSFF_BLK;
    if (blocks > need) blocks = need;
    nsff_fused_kernel<<<blocks, NSFF_BLK>>>(x, a, W1, b1, W2, b2, Ww, bw, Wk, bk,
                                            out, n4);
}